// round 1
// baseline (speedup 1.0000x reference)
#include <cuda_runtime.h>
#include <math.h>

#define NN      100000
#define NEDGE   1600000
#define F       128
#define BQ      8192
#define NSDIM   64
#define NC      16

// Scratch (allocation-free rule: __device__ globals)
__device__ float g_bufA[(size_t)NN * F];
__device__ float g_bufB[(size_t)NN * F];

#define GEMM_SMEM ((128 * 132 + 128 * 128) * 4)

// C[M,128] = transform(X[M,128]) @ W[128,128]
// FUSE: transform(v, k) = relu(v + bias[k]) applied to the X read.
template <bool FUSE>
__global__ void gemm128(const float* __restrict__ X, const float* __restrict__ W,
                        const float* __restrict__ bias, float* __restrict__ C, int M)
{
    extern __shared__ float sm[];
    float* As = sm;               // [128][132] padded
    float* Ws = sm + 128 * 132;   // [128][128]

    const int tid = threadIdx.x;        // 256 threads
    const int tx = tid & 15;            // 0..15 -> 8 output cols each
    const int ty = tid >> 4;            // 0..15 -> 8 output rows each
    const int m0 = blockIdx.x * 128;

    // Load full W tile (128x128 = 4096 float4 / 256 threads = 16 each)
    #pragma unroll
    for (int i = 0; i < 16; i++) {
        int e = i * 256 + tid;
        ((float4*)Ws)[e] = ((const float4*)W)[e];
    }

    // Load X tile (optionally fused bias+relu), zero-pad rows >= M
    #pragma unroll
    for (int i = 0; i < 16; i++) {
        int f = i * 256 + tid;          // float4 index within 128x128 tile
        int r = f >> 5;                 // row within tile
        int kc = (f & 31) << 2;         // k column (multiple of 4)
        int m = m0 + r;
        float4 v = make_float4(0.f, 0.f, 0.f, 0.f);
        if (m < M) v = *(const float4*)(X + (size_t)m * F + kc);
        if (FUSE) {
            float4 bb = *(const float4*)(bias + kc);
            v.x = fmaxf(v.x + bb.x, 0.f);
            v.y = fmaxf(v.y + bb.y, 0.f);
            v.z = fmaxf(v.z + bb.z, 0.f);
            v.w = fmaxf(v.w + bb.w, 0.f);
        }
        *(float4*)(As + r * 132 + kc) = v;
    }
    __syncthreads();

    float acc[8][8];
    #pragma unroll
    for (int i = 0; i < 8; i++)
        #pragma unroll
        for (int j = 0; j < 8; j++) acc[i][j] = 0.f;

    #pragma unroll 4
    for (int k = 0; k < 128; k++) {
        float a[8];
        #pragma unroll
        for (int i = 0; i < 8; i++) a[i] = As[(ty * 8 + i) * 132 + k];
        float4 w0 = ((const float4*)Ws)[k * 32 + tx * 2];
        float4 w1 = ((const float4*)Ws)[k * 32 + tx * 2 + 1];
        float b[8] = {w0.x, w0.y, w0.z, w0.w, w1.x, w1.y, w1.z, w1.w};
        #pragma unroll
        for (int i = 0; i < 8; i++)
            #pragma unroll
            for (int j = 0; j < 8; j++) acc[i][j] += a[i] * b[j];
    }

    #pragma unroll
    for (int i = 0; i < 8; i++) {
        int m = m0 + ty * 8 + i;
        if (m < M) {
            float4* o = (float4*)(C + (size_t)m * F + tx * 8);
            o[0] = make_float4(acc[i][0], acc[i][1], acc[i][2], acc[i][3]);
            o[1] = make_float4(acc[i][4], acc[i][5], acc[i][6], acc[i][7]);
        }
    }
}

// out[row[e]] += val[e] * H[col[e]]   (one warp per edge, lane handles 4 floats)
__global__ void spmm_coo(const int* __restrict__ row, const int* __restrict__ col,
                         const float* __restrict__ val, const float* __restrict__ H,
                         float* __restrict__ out, int ne)
{
    int w = (blockIdx.x * blockDim.x + threadIdx.x) >> 5;
    int lane = threadIdx.x & 31;
    if (w >= ne) return;
    int r = __ldg(row + w);
    int c = __ldg(col + w);
    float v = __ldg(val + w);
    float4 h = *(const float4*)(H + (size_t)c * F + lane * 4);
    float* o = out + (size_t)r * F + lane * 4;
    atomicAdd(o + 0, v * h.x);
    atomicAdd(o + 1, v * h.y);
    atomicAdd(o + 2, v * h.z);
    atomicAdd(o + 3, v * h.w);
}

// z = concat(H[index[b]] + b2, s[b]) @ Wl + bl ; out = log_softmax(z)
__global__ void final_kernel(const float* __restrict__ H, const float* __restrict__ b2,
                             const float* __restrict__ s, const int* __restrict__ index,
                             const float* __restrict__ Wl, const float* __restrict__ bl,
                             float* __restrict__ out)
{
    __shared__ float Wls[(F + NSDIM) * NC];   // 192*16
    __shared__ float bls[NC];
    __shared__ float sin[8][F + NSDIM];       // per-warp input vectors

    for (int i = threadIdx.x; i < (F + NSDIM) * NC; i += blockDim.x) Wls[i] = Wl[i];
    if (threadIdx.x < NC) bls[threadIdx.x] = bl[threadIdx.x];
    __syncthreads();

    int warp = threadIdx.x >> 5;
    int lane = threadIdx.x & 31;
    int b = blockIdx.x * 8 + warp;
    if (b >= BQ) return;

    int idx = __ldg(index + b);
    for (int k = lane; k < F; k += 32)
        sin[warp][k] = H[(size_t)idx * F + k] + b2[k];
    for (int k = lane; k < NSDIM; k += 32)
        sin[warp][F + k] = s[(size_t)b * NSDIM + k];
    __syncwarp();

    float acc = 0.f;
    if (lane < NC) {
        acc = bls[lane];
        #pragma unroll 4
        for (int k = 0; k < F + NSDIM; k++)
            acc += sin[warp][k] * Wls[k * NC + lane];
    }
    // log_softmax over 16 classes (lanes 0..15 form shuffle group)
    float m = acc;
    #pragma unroll
    for (int o = 8; o > 0; o >>= 1)
        m = fmaxf(m, __shfl_xor_sync(0xffffffffu, m, o, 16));
    float e = (lane < NC) ? expf(acc - m) : 0.f;
    float sum = e;
    #pragma unroll
    for (int o = 8; o > 0; o >>= 1)
        sum += __shfl_xor_sync(0xffffffffu, sum, o, 16);
    if (lane < NC)
        out[(size_t)b * NC + lane] = acc - m - logf(sum);
}

extern "C" void kernel_launch(void* const* d_in, const int* in_sizes, int n_in,
                              void* d_out, int out_size)
{
    const float* s    = (const float*)d_in[0];
    const float* x    = (const float*)d_in[1];
    const int*   row  = (const int*)  d_in[2];
    const int*   col  = (const int*)  d_in[3];
    const float* val  = (const float*)d_in[4];
    const int*   index= (const int*)  d_in[5];
    const float* W1   = (const float*)d_in[6];
    const float* b1   = (const float*)d_in[7];
    const float* W2   = (const float*)d_in[8];
    const float* b2   = (const float*)d_in[9];
    const float* Wl   = (const float*)d_in[10];
    const float* bl   = (const float*)d_in[11];
    float* out = (float*)d_out;

    float *A, *B;
    cudaGetSymbolAddress((void**)&A, g_bufA);
    cudaGetSymbolAddress((void**)&B, g_bufB);

    cudaFuncSetAttribute(gemm128<false>, cudaFuncAttributeMaxDynamicSharedMemorySize, GEMM_SMEM);
    cudaFuncSetAttribute(gemm128<true>,  cudaFuncAttributeMaxDynamicSharedMemorySize, GEMM_SMEM);

    const int gemm_grid = (NN + 127) / 128;          // 782
    const int spmm_grid = (NEDGE * 32 + 255) / 256;  // 200000

    // A = x @ W1
    gemm128<false><<<gemm_grid, 256, GEMM_SMEM>>>(x, W1, nullptr, A, NN);
    // B = spmm(A)
    cudaMemsetAsync(B, 0, (size_t)NN * F * sizeof(float));
    spmm_coo<<<spmm_grid, 256>>>(row, col, val, A, B, NEDGE);
    // A = relu(B + b1) @ W2
    gemm128<true><<<gemm_grid, 256, GEMM_SMEM>>>(B, W2, b1, A, NN);
    // B = spmm(A)
    cudaMemsetAsync(B, 0, (size_t)NN * F * sizeof(float));
    spmm_coo<<<spmm_grid, 256>>>(row, col, val, A, B, NEDGE);
    // out = log_softmax(concat(B[index]+b2, s) @ Wl + bl)
    final_kernel<<<(BQ + 7) / 8, 256>>>(B, b2, s, index, Wl, bl, out);
}

// round 2
// speedup vs baseline: 3.0206x; 3.0206x over previous
#include <cuda_runtime.h>
#include <math.h>

#define NN      100000
#define NEDGE   1600000
#define F       128
#define BQ      8192
#define NSDIM   64
#define NC      16

// ---------------- scratch (__device__ globals, allocation-free) ----------------
__device__ float g_bufA[(size_t)NN * F];
__device__ float g_bufB[(size_t)NN * F];
__device__ int   g_cnt[NN];          // histogram
__device__ int   g_ptr[NN + 1];      // CSR row pointers
__device__ int   g_woff[NN];         // scatter write offsets (copy of ptr)
__device__ int   g_bsum[256];        // scan block sums
__device__ int   g_pcol[NEDGE];      // permuted col
__device__ float g_pval[NEDGE];      // permuted val

#define GEMM_SMEM ((128 * 132 + 128 * 128) * 4)

// ---------------- dense 128-wide GEMM, W resident in smem ----------------
template <bool FUSE>
__global__ void gemm128(const float* __restrict__ X, const float* __restrict__ W,
                        const float* __restrict__ bias, float* __restrict__ C, int M)
{
    extern __shared__ float sm[];
    float* As = sm;               // [128][132] padded
    float* Ws = sm + 128 * 132;   // [128][128]

    const int tid = threadIdx.x;        // 256 threads
    const int tx = tid & 15;
    const int ty = tid >> 4;
    const int m0 = blockIdx.x * 128;

    #pragma unroll
    for (int i = 0; i < 16; i++) {
        int e = i * 256 + tid;
        ((float4*)Ws)[e] = ((const float4*)W)[e];
    }

    #pragma unroll
    for (int i = 0; i < 16; i++) {
        int f = i * 256 + tid;
        int r = f >> 5;
        int kc = (f & 31) << 2;
        int m = m0 + r;
        float4 v = make_float4(0.f, 0.f, 0.f, 0.f);
        if (m < M) v = *(const float4*)(X + (size_t)m * F + kc);
        if (FUSE) {
            float4 bb = *(const float4*)(bias + kc);
            v.x = fmaxf(v.x + bb.x, 0.f);
            v.y = fmaxf(v.y + bb.y, 0.f);
            v.z = fmaxf(v.z + bb.z, 0.f);
            v.w = fmaxf(v.w + bb.w, 0.f);
        }
        *(float4*)(As + r * 132 + kc) = v;
    }
    __syncthreads();

    float acc[8][8];
    #pragma unroll
    for (int i = 0; i < 8; i++)
        #pragma unroll
        for (int j = 0; j < 8; j++) acc[i][j] = 0.f;

    #pragma unroll 4
    for (int k = 0; k < 128; k++) {
        float a[8];
        #pragma unroll
        for (int i = 0; i < 8; i++) a[i] = As[(ty * 8 + i) * 132 + k];
        float4 w0 = ((const float4*)Ws)[k * 32 + tx * 2];
        float4 w1 = ((const float4*)Ws)[k * 32 + tx * 2 + 1];
        float b[8] = {w0.x, w0.y, w0.z, w0.w, w1.x, w1.y, w1.z, w1.w};
        #pragma unroll
        for (int i = 0; i < 8; i++)
            #pragma unroll
            for (int j = 0; j < 8; j++) acc[i][j] += a[i] * b[j];
    }

    #pragma unroll
    for (int i = 0; i < 8; i++) {
        int m = m0 + ty * 8 + i;
        if (m < M) {
            float4* o = (float4*)(C + (size_t)m * F + tx * 8);
            o[0] = make_float4(acc[i][0], acc[i][1], acc[i][2], acc[i][3]);
            o[1] = make_float4(acc[i][4], acc[i][5], acc[i][6], acc[i][7]);
        }
    }
}

// ---------------- CSR build ----------------
__global__ void hist_kernel(const int* __restrict__ row, int ne)
{
    int e = blockIdx.x * blockDim.x + threadIdx.x;
    if (e < ne) atomicAdd(&g_cnt[row[e]], 1);
}

// exclusive scan, stage 1: 1024 elems/block (256 thr x 4)
__global__ void scan1_kernel(int n)
{
    __shared__ int sm[256];
    int tid = threadIdx.x;
    int base = blockIdx.x * 1024 + tid * 4;
    int v[4];
    #pragma unroll
    for (int i = 0; i < 4; i++)
        v[i] = (base + i < n) ? g_cnt[base + i] : 0;
    int tsum = v[0] + v[1] + v[2] + v[3];
    sm[tid] = tsum;
    __syncthreads();
    // inclusive scan of sm
    #pragma unroll
    for (int o = 1; o < 256; o <<= 1) {
        int t = (tid >= o) ? sm[tid - o] : 0;
        __syncthreads();
        sm[tid] += t;
        __syncthreads();
    }
    int prefix = sm[tid] - tsum;   // exclusive prefix for this thread
    int run = prefix;
    #pragma unroll
    for (int i = 0; i < 4; i++) {
        if (base + i < n) g_ptr[base + i] = run;
        run += v[i];
    }
    if (tid == 255) g_bsum[blockIdx.x] = sm[255];
}

// stage 2: scan block sums (<=256 blocks) in one block, exclusive in place
__global__ void scan2_kernel(int nb)
{
    __shared__ int sm[256];
    int tid = threadIdx.x;
    sm[tid] = (tid < nb) ? g_bsum[tid] : 0;
    __syncthreads();
    #pragma unroll
    for (int o = 1; o < 256; o <<= 1) {
        int t = (tid >= o) ? sm[tid - o] : 0;
        __syncthreads();
        sm[tid] += t;
        __syncthreads();
    }
    int val = (tid < nb) ? ((tid == 0) ? 0 : sm[tid - 1]) : 0;
    if (tid < nb) g_bsum[tid] = val;
}

// stage 3: add block offsets, copy to woff, set ptr[NN]
__global__ void scan3_kernel(int n, int ne)
{
    int i = blockIdx.x * blockDim.x + threadIdx.x;
    if (i < n) {
        int p = g_ptr[i] + g_bsum[i >> 10];
        g_ptr[i] = p;
        g_woff[i] = p;
    }
    if (i == 0) g_ptr[n] = ne;
}

__global__ void scatter_kernel(const int* __restrict__ row, const int* __restrict__ col,
                               const float* __restrict__ val, int ne)
{
    int e = blockIdx.x * blockDim.x + threadIdx.x;
    if (e < ne) {
        int r = row[e];
        int p = atomicAdd(&g_woff[r], 1);
        g_pcol[p] = col[e];
        g_pval[p] = val[e];
    }
}

// ---------------- SPMM, CSR form: one warp per output row, no atomics ----------------
__global__ void spmm_csr(const float* __restrict__ H, float* __restrict__ out)
{
    int warp = threadIdx.x >> 5;
    int lane = threadIdx.x & 31;
    int r = blockIdx.x * 8 + warp;
    if (r >= NN) return;

    int e0 = g_ptr[r];
    int e1 = g_ptr[r + 1];

    float4 acc = make_float4(0.f, 0.f, 0.f, 0.f);
    int e = e0;
    // 4-way unrolled: 4 independent gathers in flight
    for (; e + 4 <= e1; e += 4) {
        int   c0 = g_pcol[e],     c1 = g_pcol[e + 1], c2 = g_pcol[e + 2], c3 = g_pcol[e + 3];
        float v0 = g_pval[e],     v1 = g_pval[e + 1], v2 = g_pval[e + 2], v3 = g_pval[e + 3];
        float4 h0 = *(const float4*)(H + (size_t)c0 * F + lane * 4);
        float4 h1 = *(const float4*)(H + (size_t)c1 * F + lane * 4);
        float4 h2 = *(const float4*)(H + (size_t)c2 * F + lane * 4);
        float4 h3 = *(const float4*)(H + (size_t)c3 * F + lane * 4);
        acc.x += v0 * h0.x; acc.y += v0 * h0.y; acc.z += v0 * h0.z; acc.w += v0 * h0.w;
        acc.x += v1 * h1.x; acc.y += v1 * h1.y; acc.z += v1 * h1.z; acc.w += v1 * h1.w;
        acc.x += v2 * h2.x; acc.y += v2 * h2.y; acc.z += v2 * h2.z; acc.w += v2 * h2.w;
        acc.x += v3 * h3.x; acc.y += v3 * h3.y; acc.z += v3 * h3.z; acc.w += v3 * h3.w;
    }
    for (; e < e1; e++) {
        int c = g_pcol[e];
        float v = g_pval[e];
        float4 h = *(const float4*)(H + (size_t)c * F + lane * 4);
        acc.x += v * h.x; acc.y += v * h.y; acc.z += v * h.z; acc.w += v * h.w;
    }
    *(float4*)(out + (size_t)r * F + lane * 4) = acc;
}

// ---------------- final: gather + concat + linear + log_softmax ----------------
__global__ void final_kernel(const float* __restrict__ H, const float* __restrict__ b2,
                             const float* __restrict__ s, const int* __restrict__ index,
                             const float* __restrict__ Wl, const float* __restrict__ bl,
                             float* __restrict__ out)
{
    __shared__ float Wls[(F + NSDIM) * NC];
    __shared__ float bls[NC];
    __shared__ float sin[8][F + NSDIM];

    for (int i = threadIdx.x; i < (F + NSDIM) * NC; i += blockDim.x) Wls[i] = Wl[i];
    if (threadIdx.x < NC) bls[threadIdx.x] = bl[threadIdx.x];
    __syncthreads();

    int warp = threadIdx.x >> 5;
    int lane = threadIdx.x & 31;
    int b = blockIdx.x * 8 + warp;
    if (b >= BQ) return;

    int idx = __ldg(index + b);
    for (int k = lane; k < F; k += 32)
        sin[warp][k] = H[(size_t)idx * F + k] + b2[k];
    for (int k = lane; k < NSDIM; k += 32)
        sin[warp][F + k] = s[(size_t)b * NSDIM + k];
    __syncwarp();

    float acc = 0.f;
    if (lane < NC) {
        acc = bls[lane];
        #pragma unroll 4
        for (int k = 0; k < F + NSDIM; k++)
            acc += sin[warp][k] * Wls[k * NC + lane];
    }
    float m = acc;
    #pragma unroll
    for (int o = 8; o > 0; o >>= 1)
        m = fmaxf(m, __shfl_xor_sync(0xffffffffu, m, o, 16));
    float e = (lane < NC) ? expf(acc - m) : 0.f;
    float sum = e;
    #pragma unroll
    for (int o = 8; o > 0; o >>= 1)
        sum += __shfl_xor_sync(0xffffffffu, sum, o, 16);
    if (lane < NC)
        out[(size_t)b * NC + lane] = acc - m - logf(sum);
}

// ---------------- launch ----------------
extern "C" void kernel_launch(void* const* d_in, const int* in_sizes, int n_in,
                              void* d_out, int out_size)
{
    const float* s    = (const float*)d_in[0];
    const float* x    = (const float*)d_in[1];
    const int*   row  = (const int*)  d_in[2];
    const int*   col  = (const int*)  d_in[3];
    const float* val  = (const float*)d_in[4];
    const int*   index= (const int*)  d_in[5];
    const float* W1   = (const float*)d_in[6];
    const float* b1   = (const float*)d_in[7];
    const float* W2   = (const float*)d_in[8];
    const float* b2   = (const float*)d_in[9];
    const float* Wl   = (const float*)d_in[10];
    const float* bl   = (const float*)d_in[11];
    float* out = (float*)d_out;

    float *A, *B;
    int *cntp;
    cudaGetSymbolAddress((void**)&A, g_bufA);
    cudaGetSymbolAddress((void**)&B, g_bufB);
    cudaGetSymbolAddress((void**)&cntp, g_cnt);

    cudaFuncSetAttribute(gemm128<false>, cudaFuncAttributeMaxDynamicSharedMemorySize, GEMM_SMEM);
    cudaFuncSetAttribute(gemm128<true>,  cudaFuncAttributeMaxDynamicSharedMemorySize, GEMM_SMEM);

    const int gemm_grid  = (NN + 127) / 128;           // 782
    const int edge_grid  = (NEDGE + 255) / 256;        // 6250
    const int scan_nb    = (NN + 1023) / 1024;         // 98
    const int spmm_grid  = (NN + 7) / 8;               // 12500

    // ---- CSR build (independent of GEMM1; shared by both SPMMs) ----
    cudaMemsetAsync(cntp, 0, NN * sizeof(int));
    hist_kernel<<<edge_grid, 256>>>(row, NEDGE);
    scan1_kernel<<<scan_nb, 256>>>(NN);
    scan2_kernel<<<1, 256>>>(scan_nb);
    scan3_kernel<<<(NN + 255) / 256, 256>>>(NN, NEDGE);
    scatter_kernel<<<edge_grid, 256>>>(row, col, val, NEDGE);

    // ---- pipeline ----
    gemm128<false><<<gemm_grid, 256, GEMM_SMEM>>>(x, W1, nullptr, A, NN);
    spmm_csr<<<spmm_grid, 256>>>(A, B);
    gemm128<true><<<gemm_grid, 256, GEMM_SMEM>>>(B, W2, b1, A, NN);
    spmm_csr<<<spmm_grid, 256>>>(A, B);
    final_kernel<<<(BQ + 7) / 8, 256>>>(B, b2, s, index, Wl, bl, out);
}

// round 4
// speedup vs baseline: 5.3821x; 1.7818x over previous
#include <cuda_runtime.h>
#include <cstdint>
#include <math.h>

#define NN      100000
#define NEDGE   1600000
#define F       128
#define BQ      8192
#define NSDIM   64
#define NC      16

// ---------------- scratch (__device__ globals, allocation-free) ----------------
__device__ float g_bufA[(size_t)NN * F];
__device__ float g_bufB[(size_t)NN * F];
__device__ int   g_cnt[NN];
__device__ int   g_ptr[NN + 1];
__device__ int   g_woff[NN];
__device__ int   g_bsum[256];
__device__ int   g_pcol[NEDGE];
__device__ float g_pval[NEDGE];

// A tile: 128 x 132 (pad 4), W tile: 128 x 136 (pad 8), both tf32-in-u32
#define AS_STRIDE 132
#define WS_STRIDE 136
#define GEMM_SMEM ((128 * AS_STRIDE + 128 * WS_STRIDE) * 4)

__device__ __forceinline__ unsigned int f2tf32(float f) {
    unsigned int r;
    asm("cvt.rna.tf32.f32 %0, %1;" : "=r"(r) : "f"(f));
    return r;
}

// ---------------- tf32 tensor-core GEMM: C[M,128] = transform(X) @ W ----------------
// FUSE: relu(x + bias) applied to X elements on load.
template <bool FUSE>
__global__ void gemm128_tc(const float* __restrict__ X, const float* __restrict__ W,
                           const float* __restrict__ bias, float* __restrict__ C, int M)
{
    extern __shared__ unsigned int smu[];
    unsigned int* As = smu;                    // [128][132]  layout [m][k]
    unsigned int* Ws = smu + 128 * AS_STRIDE;  // [128][136]  layout [k][n]

    const int tid  = threadIdx.x;          // 256 threads, 8 warps
    const int wid  = tid >> 5;
    const int lane = tid & 31;
    const int gid  = lane >> 2;            // 0..7
    const int tig  = lane & 3;             // 0..3
    const int wm   = wid & 3;              // 4 warps over M (32 rows each)
    const int wn   = wid >> 2;             // 2 warps over N (64 cols each)
    const int m0   = blockIdx.x * 128;

    // Load W -> Ws[k][n] (tf32), 4096 float4 over 256 threads
    #pragma unroll
    for (int i = 0; i < 16; i++) {
        int e = i * 256 + tid;
        int k = e >> 5;
        int n4 = (e & 31) << 2;
        float4 w = *(const float4*)(W + k * F + n4);
        uint4 u = make_uint4(f2tf32(w.x), f2tf32(w.y), f2tf32(w.z), f2tf32(w.w));
        *(uint4*)(Ws + k * WS_STRIDE + n4) = u;
    }

    // Load X tile -> As[r][k] (tf32), optional fused bias+relu
    #pragma unroll
    for (int i = 0; i < 16; i++) {
        int e = i * 256 + tid;
        int r = e >> 5;
        int kc = (e & 31) << 2;
        int m = m0 + r;
        float4 v = make_float4(0.f, 0.f, 0.f, 0.f);
        if (m < M) v = *(const float4*)(X + (size_t)m * F + kc);
        if (FUSE) {
            float4 bb = *(const float4*)(bias + kc);
            v.x = fmaxf(v.x + bb.x, 0.f);
            v.y = fmaxf(v.y + bb.y, 0.f);
            v.z = fmaxf(v.z + bb.z, 0.f);
            v.w = fmaxf(v.w + bb.w, 0.f);
        }
        uint4 u = make_uint4(f2tf32(v.x), f2tf32(v.y), f2tf32(v.z), f2tf32(v.w));
        *(uint4*)(As + r * AS_STRIDE + kc) = u;
    }
    __syncthreads();

    // Accumulators: warp tile 32(M) x 64(N) = 2 mfrag x 8 nfrag x 4 regs
    float acc[2][8][4];
    #pragma unroll
    for (int a = 0; a < 2; a++)
        #pragma unroll
        for (int b = 0; b < 8; b++)
            #pragma unroll
            for (int c = 0; c < 4; c++) acc[a][b][c] = 0.f;

    #pragma unroll 4
    for (int ks = 0; ks < 16; ks++) {
        const int k0 = ks * 8;
        unsigned int afr[2][4];
        #pragma unroll
        for (int mf = 0; mf < 2; mf++) {
            int rb = wm * 32 + mf * 16 + gid;
            afr[mf][0] = As[rb * AS_STRIDE + k0 + tig];
            afr[mf][1] = As[(rb + 8) * AS_STRIDE + k0 + tig];
            afr[mf][2] = As[rb * AS_STRIDE + k0 + 4 + tig];
            afr[mf][3] = As[(rb + 8) * AS_STRIDE + k0 + 4 + tig];
        }
        unsigned int bfr[8][2];
        #pragma unroll
        for (int nf = 0; nf < 8; nf++) {
            int nb = wn * 64 + nf * 8 + gid;
            bfr[nf][0] = Ws[(k0 + tig) * WS_STRIDE + nb];
            bfr[nf][1] = Ws[(k0 + 4 + tig) * WS_STRIDE + nb];
        }
        #pragma unroll
        for (int mf = 0; mf < 2; mf++)
            #pragma unroll
            for (int nf = 0; nf < 8; nf++) {
                asm volatile(
                    "mma.sync.aligned.m16n8k8.row.col.f32.tf32.tf32.f32 "
                    "{%0,%1,%2,%3}, {%4,%5,%6,%7}, {%8,%9}, {%0,%1,%2,%3};"
                    : "+f"(acc[mf][nf][0]), "+f"(acc[mf][nf][1]),
                      "+f"(acc[mf][nf][2]), "+f"(acc[mf][nf][3])
                    : "r"(afr[mf][0]), "r"(afr[mf][1]), "r"(afr[mf][2]), "r"(afr[mf][3]),
                      "r"(bfr[nf][0]), "r"(bfr[nf][1]));
            }
    }

    // Store C
    #pragma unroll
    for (int mf = 0; mf < 2; mf++) {
        int r0 = m0 + wm * 32 + mf * 16 + gid;
        #pragma unroll
        for (int nf = 0; nf < 8; nf++) {
            int ccol = wn * 64 + nf * 8 + tig * 2;
            if (r0 < M)
                *(float2*)(C + (size_t)r0 * F + ccol) =
                    make_float2(acc[mf][nf][0], acc[mf][nf][1]);
            if (r0 + 8 < M)
                *(float2*)(C + (size_t)(r0 + 8) * F + ccol) =
                    make_float2(acc[mf][nf][2], acc[mf][nf][3]);
        }
    }
}

// ---------------- CSR build ----------------
__global__ void hist_kernel(const int* __restrict__ row, int ne)
{
    int e = blockIdx.x * blockDim.x + threadIdx.x;
    if (e < ne) atomicAdd(&g_cnt[row[e]], 1);
}

__global__ void scan1_kernel(int n)
{
    __shared__ int sm[256];
    int tid = threadIdx.x;
    int base = blockIdx.x * 1024 + tid * 4;
    int v[4];
    #pragma unroll
    for (int i = 0; i < 4; i++)
        v[i] = (base + i < n) ? g_cnt[base + i] : 0;
    int tsum = v[0] + v[1] + v[2] + v[3];
    sm[tid] = tsum;
    __syncthreads();
    #pragma unroll
    for (int o = 1; o < 256; o <<= 1) {
        int t = (tid >= o) ? sm[tid - o] : 0;
        __syncthreads();
        sm[tid] += t;
        __syncthreads();
    }
    int run = sm[tid] - tsum;
    #pragma unroll
    for (int i = 0; i < 4; i++) {
        if (base + i < n) g_ptr[base + i] = run;
        run += v[i];
    }
    if (tid == 255) g_bsum[blockIdx.x] = sm[255];
}

__global__ void scan2_kernel(int nb)
{
    __shared__ int sm[256];
    int tid = threadIdx.x;
    sm[tid] = (tid < nb) ? g_bsum[tid] : 0;
    __syncthreads();
    #pragma unroll
    for (int o = 1; o < 256; o <<= 1) {
        int t = (tid >= o) ? sm[tid - o] : 0;
        __syncthreads();
        sm[tid] += t;
        __syncthreads();
    }
    if (tid < nb) g_bsum[tid] = (tid == 0) ? 0 : sm[tid - 1];
}

__global__ void scan3_kernel(int n, int ne)
{
    int i = blockIdx.x * blockDim.x + threadIdx.x;
    if (i < n) {
        int p = g_ptr[i] + g_bsum[i >> 10];
        g_ptr[i] = p;
        g_woff[i] = p;
    }
    if (i == 0) g_ptr[n] = ne;
}

__global__ void scatter_kernel(const int* __restrict__ row, const int* __restrict__ col,
                               const float* __restrict__ val, int ne)
{
    int e = blockIdx.x * blockDim.x + threadIdx.x;
    if (e < ne) {
        int r = row[e];
        int p = atomicAdd(&g_woff[r], 1);
        g_pcol[p] = col[e];
        g_pval[p] = val[e];
    }
}

// ---------------- SPMM1 (full, CSR, warp per row, no atomics) ----------------
__global__ void spmm_csr(const float* __restrict__ H, float* __restrict__ out)
{
    int warp = threadIdx.x >> 5;
    int lane = threadIdx.x & 31;
    int r = blockIdx.x * 8 + warp;
    if (r >= NN) return;

    int e0 = g_ptr[r];
    int e1 = g_ptr[r + 1];

    float4 acc = make_float4(0.f, 0.f, 0.f, 0.f);
    int e = e0;
    for (; e + 4 <= e1; e += 4) {
        int   c0 = g_pcol[e],     c1 = g_pcol[e + 1], c2 = g_pcol[e + 2], c3 = g_pcol[e + 3];
        float v0 = g_pval[e],     v1 = g_pval[e + 1], v2 = g_pval[e + 2], v3 = g_pval[e + 3];
        float4 h0 = *(const float4*)(H + (size_t)c0 * F + lane * 4);
        float4 h1 = *(const float4*)(H + (size_t)c1 * F + lane * 4);
        float4 h2 = *(const float4*)(H + (size_t)c2 * F + lane * 4);
        float4 h3 = *(const float4*)(H + (size_t)c3 * F + lane * 4);
        acc.x += v0 * h0.x; acc.y += v0 * h0.y; acc.z += v0 * h0.z; acc.w += v0 * h0.w;
        acc.x += v1 * h1.x; acc.y += v1 * h1.y; acc.z += v1 * h1.z; acc.w += v1 * h1.w;
        acc.x += v2 * h2.x; acc.y += v2 * h2.y; acc.z += v2 * h2.z; acc.w += v2 * h2.w;
        acc.x += v3 * h3.x; acc.y += v3 * h3.y; acc.z += v3 * h3.z; acc.w += v3 * h3.w;
    }
    for (; e < e1; e++) {
        int c = g_pcol[e];
        float v = g_pval[e];
        float4 h = *(const float4*)(H + (size_t)c * F + lane * 4);
        acc.x += v * h.x; acc.y += v * h.y; acc.z += v * h.z; acc.w += v * h.w;
    }
    *(float4*)(out + (size_t)r * F + lane * 4) = acc;
}

// ---------------- fused: row-restricted SPMM2 + concat + linear + log_softmax ----------------
__global__ void spmm2_final(const float* __restrict__ H2, const float* __restrict__ b2,
                            const float* __restrict__ s, const int* __restrict__ index,
                            const float* __restrict__ Wl, const float* __restrict__ bl,
                            float* __restrict__ out)
{
    __shared__ float Wls[(F + NSDIM) * NC];
    __shared__ float bls[NC];
    __shared__ float sin[8][F + NSDIM];

    for (int i = threadIdx.x; i < (F + NSDIM) * NC; i += blockDim.x) Wls[i] = Wl[i];
    if (threadIdx.x < NC) bls[threadIdx.x] = bl[threadIdx.x];
    __syncthreads();

    int warp = threadIdx.x >> 5;
    int lane = threadIdx.x & 31;
    int b = blockIdx.x * 8 + warp;
    if (b >= BQ) return;

    int r = __ldg(index + b);
    int e0 = g_ptr[r];
    int e1 = g_ptr[r + 1];

    float4 acc = make_float4(0.f, 0.f, 0.f, 0.f);
    int e = e0;
    for (; e + 4 <= e1; e += 4) {
        int   c0 = g_pcol[e],     c1 = g_pcol[e + 1], c2 = g_pcol[e + 2], c3 = g_pcol[e + 3];
        float v0 = g_pval[e],     v1 = g_pval[e + 1], v2 = g_pval[e + 2], v3 = g_pval[e + 3];
        float4 h0 = *(const float4*)(H2 + (size_t)c0 * F + lane * 4);
        float4 h1 = *(const float4*)(H2 + (size_t)c1 * F + lane * 4);
        float4 h2 = *(const float4*)(H2 + (size_t)c2 * F + lane * 4);
        float4 h3 = *(const float4*)(H2 + (size_t)c3 * F + lane * 4);
        acc.x += v0 * h0.x; acc.y += v0 * h0.y; acc.z += v0 * h0.z; acc.w += v0 * h0.w;
        acc.x += v1 * h1.x; acc.y += v1 * h1.y; acc.z += v1 * h1.z; acc.w += v1 * h1.w;
        acc.x += v2 * h2.x; acc.y += v2 * h2.y; acc.z += v2 * h2.z; acc.w += v2 * h2.w;
        acc.x += v3 * h3.x; acc.y += v3 * h3.y; acc.z += v3 * h3.z; acc.w += v3 * h3.w;
    }
    for (; e < e1; e++) {
        int c = g_pcol[e];
        float v = g_pval[e];
        float4 h = *(const float4*)(H2 + (size_t)c * F + lane * 4);
        acc.x += v * h.x; acc.y += v * h.y; acc.z += v * h.z; acc.w += v * h.w;
    }

    float4 bb = *(const float4*)(b2 + lane * 4);
    sin[warp][lane * 4 + 0] = acc.x + bb.x;
    sin[warp][lane * 4 + 1] = acc.y + bb.y;
    sin[warp][lane * 4 + 2] = acc.z + bb.z;
    sin[warp][lane * 4 + 3] = acc.w + bb.w;
    #pragma unroll
    for (int k = lane; k < NSDIM; k += 32)
        sin[warp][F + k] = s[(size_t)b * NSDIM + k];
    __syncwarp();

    float z = 0.f;
    if (lane < NC) {
        z = bls[lane];
        #pragma unroll 4
        for (int k = 0; k < F + NSDIM; k++)
            z += sin[warp][k] * Wls[k * NC + lane];
    }
    float m = z;
    #pragma unroll
    for (int o = 8; o > 0; o >>= 1)
        m = fmaxf(m, __shfl_xor_sync(0xffffffffu, m, o, 16));
    float ex = (lane < NC) ? expf(z - m) : 0.f;
    float sum = ex;
    #pragma unroll
    for (int o = 8; o > 0; o >>= 1)
        sum += __shfl_xor_sync(0xffffffffu, sum, o, 16);
    if (lane < NC)
        out[(size_t)b * NC + lane] = z - m - logf(sum);
}

// ---------------- launch ----------------
extern "C" void kernel_launch(void* const* d_in, const int* in_sizes, int n_in,
                              void* d_out, int out_size)
{
    const float* s    = (const float*)d_in[0];
    const float* x    = (const float*)d_in[1];
    const int*   row  = (const int*)  d_in[2];
    const int*   col  = (const int*)  d_in[3];
    const float* val  = (const float*)d_in[4];
    const int*   index= (const int*)  d_in[5];
    const float* W1   = (const float*)d_in[6];
    const float* b1   = (const float*)d_in[7];
    const float* W2   = (const float*)d_in[8];
    const float* b2   = (const float*)d_in[9];
    const float* Wl   = (const float*)d_in[10];
    const float* bl   = (const float*)d_in[11];
    float* out = (float*)d_out;

    float *A, *B;
    int *cntp;
    cudaGetSymbolAddress((void**)&A, g_bufA);
    cudaGetSymbolAddress((void**)&B, g_bufB);
    cudaGetSymbolAddress((void**)&cntp, g_cnt);

    cudaFuncSetAttribute(gemm128_tc<false>, cudaFuncAttributeMaxDynamicSharedMemorySize, GEMM_SMEM);
    cudaFuncSetAttribute(gemm128_tc<true>,  cudaFuncAttributeMaxDynamicSharedMemorySize, GEMM_SMEM);

    const int gemm_grid  = (NN + 127) / 128;           // 782
    const int edge_grid  = (NEDGE + 255) / 256;        // 6250
    const int scan_nb    = (NN + 1023) / 1024;         // 98
    const int spmm_grid  = (NN + 7) / 8;               // 12500

    // ---- CSR build ----
    cudaMemsetAsync(cntp, 0, NN * sizeof(int));
    hist_kernel<<<edge_grid, 256>>>(row, NEDGE);
    scan1_kernel<<<scan_nb, 256>>>(NN);
    scan2_kernel<<<1, 256>>>(scan_nb);
    scan3_kernel<<<(NN + 255) / 256, 256>>>(NN, NEDGE);
    scatter_kernel<<<edge_grid, 256>>>(row, col, val, NEDGE);

    // ---- pipeline ----
    gemm128_tc<false><<<gemm_grid, 256, GEMM_SMEM>>>(x, W1, nullptr, A, NN);
    spmm_csr<<<spmm_grid, 256>>>(A, B);
    gemm128_tc<true><<<gemm_grid, 256, GEMM_SMEM>>>(B, W2, b1, A, NN);
    spmm2_final<<<(BQ + 7) / 8, 256>>>(A, b2, s, index, Wl, bl, out);
}

// round 5
// speedup vs baseline: 5.9491x; 1.1054x over previous
#include <cuda_runtime.h>
#include <cuda_fp16.h>
#include <cstdint>
#include <math.h>

#define NN      100000
#define NEDGE   1600000
#define F       128
#define BQ      8192
#define NSDIM   64
#define NC      16

// ---------------- scratch (__device__ globals, allocation-free) ----------------
__device__ __half g_bufA[(size_t)NN * F];   // GEMM outputs (fp16)
__device__ __half g_bufB[(size_t)NN * F];   // SPMM1 output (fp16)
__device__ int    g_cnt[NN];
__device__ int    g_ptr[NN + 1];
__device__ int    g_woff[NN];
__device__ int    g_bsum[256];
__device__ int    g_pcol[NEDGE];
__device__ float  g_pval[NEDGE];

#define AS_STRIDE 132
#define WS_STRIDE 136
#define GEMM_SMEM ((128 * AS_STRIDE + 128 * WS_STRIDE) * 4)

__device__ __forceinline__ unsigned int f2tf32(float f) {
    unsigned int r;
    asm("cvt.rna.tf32.f32 %0, %1;" : "=r"(r) : "f"(f));
    return r;
}

// ---------------- tf32 tensor-core GEMM: C[M,128](fp16) = transform(X) @ W ----------------
// FUSE=false: X fp32, no transform.  FUSE=true: X fp16, relu(x + bias).
template <bool FUSE>
__global__ void gemm128_tc(const void* __restrict__ Xv, const float* __restrict__ W,
                           const float* __restrict__ bias, __half* __restrict__ C, int M)
{
    extern __shared__ unsigned int smu[];
    unsigned int* As = smu;                    // [128][132]  [m][k]
    unsigned int* Ws = smu + 128 * AS_STRIDE;  // [128][136]  [k][n]

    const int tid  = threadIdx.x;          // 256 threads, 8 warps
    const int wid  = tid >> 5;
    const int lane = tid & 31;
    const int gid  = lane >> 2;
    const int tig  = lane & 3;
    const int wm   = wid & 3;
    const int wn   = wid >> 2;
    const int m0   = blockIdx.x * 128;

    // W -> Ws[k][n] (tf32)
    #pragma unroll
    for (int i = 0; i < 16; i++) {
        int e = i * 256 + tid;
        int k = e >> 5;
        int n4 = (e & 31) << 2;
        float4 w = *(const float4*)(W + k * F + n4);
        uint4 u = make_uint4(f2tf32(w.x), f2tf32(w.y), f2tf32(w.z), f2tf32(w.w));
        *(uint4*)(Ws + k * WS_STRIDE + n4) = u;
    }

    // X tile -> As[m][k] (tf32)
    if (FUSE) {
        const __half* Xh = (const __half*)Xv;
        #pragma unroll
        for (int i = 0; i < 8; i++) {
            int e = i * 256 + tid;          // chunk of 8 halves
            int r = e >> 4;
            int kc = (e & 15) << 3;
            int m = m0 + r;
            uint4 raw = make_uint4(0u, 0u, 0u, 0u);
            if (m < M) raw = *(const uint4*)(Xh + (size_t)m * F + kc);
            const __half2* hp = (const __half2*)&raw;
            #pragma unroll
            for (int j = 0; j < 4; j++) {
                float2 f = __half22float2(hp[j]);
                float2 bb = *(const float2*)(bias + kc + j * 2);
                f.x = fmaxf(f.x + bb.x, 0.f);
                f.y = fmaxf(f.y + bb.y, 0.f);
                As[r * AS_STRIDE + kc + j * 2]     = f2tf32(f.x);
                As[r * AS_STRIDE + kc + j * 2 + 1] = f2tf32(f.y);
            }
        }
    } else {
        const float* Xf = (const float*)Xv;
        #pragma unroll
        for (int i = 0; i < 16; i++) {
            int e = i * 256 + tid;
            int r = e >> 5;
            int kc = (e & 31) << 2;
            int m = m0 + r;
            float4 v = make_float4(0.f, 0.f, 0.f, 0.f);
            if (m < M) v = *(const float4*)(Xf + (size_t)m * F + kc);
            uint4 u = make_uint4(f2tf32(v.x), f2tf32(v.y), f2tf32(v.z), f2tf32(v.w));
            *(uint4*)(As + r * AS_STRIDE + kc) = u;
        }
    }
    __syncthreads();

    float acc[2][8][4];
    #pragma unroll
    for (int a = 0; a < 2; a++)
        #pragma unroll
        for (int b = 0; b < 8; b++)
            #pragma unroll
            for (int c = 0; c < 4; c++) acc[a][b][c] = 0.f;

    #pragma unroll 4
    for (int ks = 0; ks < 16; ks++) {
        const int k0 = ks * 8;
        unsigned int afr[2][4];
        #pragma unroll
        for (int mf = 0; mf < 2; mf++) {
            int rb = wm * 32 + mf * 16 + gid;
            afr[mf][0] = As[rb * AS_STRIDE + k0 + tig];
            afr[mf][1] = As[(rb + 8) * AS_STRIDE + k0 + tig];
            afr[mf][2] = As[rb * AS_STRIDE + k0 + 4 + tig];
            afr[mf][3] = As[(rb + 8) * AS_STRIDE + k0 + 4 + tig];
        }
        unsigned int bfr[8][2];
        #pragma unroll
        for (int nf = 0; nf < 8; nf++) {
            int nb = wn * 64 + nf * 8 + gid;
            bfr[nf][0] = Ws[(k0 + tig) * WS_STRIDE + nb];
            bfr[nf][1] = Ws[(k0 + 4 + tig) * WS_STRIDE + nb];
        }
        #pragma unroll
        for (int mf = 0; mf < 2; mf++)
            #pragma unroll
            for (int nf = 0; nf < 8; nf++) {
                asm volatile(
                    "mma.sync.aligned.m16n8k8.row.col.f32.tf32.tf32.f32 "
                    "{%0,%1,%2,%3}, {%4,%5,%6,%7}, {%8,%9}, {%0,%1,%2,%3};"
                    : "+f"(acc[mf][nf][0]), "+f"(acc[mf][nf][1]),
                      "+f"(acc[mf][nf][2]), "+f"(acc[mf][nf][3])
                    : "r"(afr[mf][0]), "r"(afr[mf][1]), "r"(afr[mf][2]), "r"(afr[mf][3]),
                      "r"(bfr[nf][0]), "r"(bfr[nf][1]));
            }
    }

    // Store C in fp16
    #pragma unroll
    for (int mf = 0; mf < 2; mf++) {
        int r0 = m0 + wm * 32 + mf * 16 + gid;
        #pragma unroll
        for (int nf = 0; nf < 8; nf++) {
            int ccol = wn * 64 + nf * 8 + tig * 2;
            if (r0 < M)
                *(__half2*)(C + (size_t)r0 * F + ccol) =
                    __floats2half2_rn(acc[mf][nf][0], acc[mf][nf][1]);
            if (r0 + 8 < M)
                *(__half2*)(C + (size_t)(r0 + 8) * F + ccol) =
                    __floats2half2_rn(acc[mf][nf][2], acc[mf][nf][3]);
        }
    }
}

// ---------------- CSR build ----------------
__global__ void hist_kernel(const int* __restrict__ row, int ne)
{
    int e = blockIdx.x * blockDim.x + threadIdx.x;
    if (e < ne) atomicAdd(&g_cnt[row[e]], 1);
}

__global__ void scan1_kernel(int n)
{
    __shared__ int sm[256];
    int tid = threadIdx.x;
    int base = blockIdx.x * 1024 + tid * 4;
    int v[4];
    #pragma unroll
    for (int i = 0; i < 4; i++)
        v[i] = (base + i < n) ? g_cnt[base + i] : 0;
    int tsum = v[0] + v[1] + v[2] + v[3];
    sm[tid] = tsum;
    __syncthreads();
    #pragma unroll
    for (int o = 1; o < 256; o <<= 1) {
        int t = (tid >= o) ? sm[tid - o] : 0;
        __syncthreads();
        sm[tid] += t;
        __syncthreads();
    }
    int run = sm[tid] - tsum;
    #pragma unroll
    for (int i = 0; i < 4; i++) {
        if (base + i < n) g_ptr[base + i] = run;
        run += v[i];
    }
    if (tid == 255) g_bsum[blockIdx.x] = sm[255];
}

__global__ void scan2_kernel(int nb)
{
    __shared__ int sm[256];
    int tid = threadIdx.x;
    sm[tid] = (tid < nb) ? g_bsum[tid] : 0;
    __syncthreads();
    #pragma unroll
    for (int o = 1; o < 256; o <<= 1) {
        int t = (tid >= o) ? sm[tid - o] : 0;
        __syncthreads();
        sm[tid] += t;
        __syncthreads();
    }
    if (tid < nb) g_bsum[tid] = (tid == 0) ? 0 : sm[tid - 1];
}

__global__ void scan3_kernel(int n, int ne)
{
    int i = blockIdx.x * blockDim.x + threadIdx.x;
    if (i < n) {
        int p = g_ptr[i] + g_bsum[i >> 10];
        g_ptr[i] = p;
        g_woff[i] = p;
    }
    if (i == 0) g_ptr[n] = ne;
}

__global__ void scatter_kernel(const int* __restrict__ row, const int* __restrict__ col,
                               const float* __restrict__ val, int ne)
{
    int e = blockIdx.x * blockDim.x + threadIdx.x;
    if (e < ne) {
        int r = row[e];
        int p = atomicAdd(&g_woff[r], 1);
        g_pcol[p] = col[e];
        g_pval[p] = val[e];
    }
}

// ---------------- SPMM1: fp16 gather, fp32 accumulate, fp16 store ----------------
__global__ void spmm_csr(const __half* __restrict__ H, __half* __restrict__ out)
{
    int warp = threadIdx.x >> 5;
    int lane = threadIdx.x & 31;
    int r = blockIdx.x * 8 + warp;
    if (r >= NN) return;

    int e0 = g_ptr[r];
    int e1 = g_ptr[r + 1];

    float4 acc = make_float4(0.f, 0.f, 0.f, 0.f);
    int e = e0;
    for (; e + 4 <= e1; e += 4) {
        int   c0 = g_pcol[e],     c1 = g_pcol[e + 1], c2 = g_pcol[e + 2], c3 = g_pcol[e + 3];
        float v0 = g_pval[e],     v1 = g_pval[e + 1], v2 = g_pval[e + 2], v3 = g_pval[e + 3];
        uint2 r0 = *(const uint2*)(H + (size_t)c0 * F + lane * 4);
        uint2 r1 = *(const uint2*)(H + (size_t)c1 * F + lane * 4);
        uint2 r2 = *(const uint2*)(H + (size_t)c2 * F + lane * 4);
        uint2 r3 = *(const uint2*)(H + (size_t)c3 * F + lane * 4);
        float2 a0 = __half22float2(*(const __half2*)&r0.x), b0 = __half22float2(*(const __half2*)&r0.y);
        float2 a1 = __half22float2(*(const __half2*)&r1.x), b1 = __half22float2(*(const __half2*)&r1.y);
        float2 a2 = __half22float2(*(const __half2*)&r2.x), b2 = __half22float2(*(const __half2*)&r2.y);
        float2 a3 = __half22float2(*(const __half2*)&r3.x), b3 = __half22float2(*(const __half2*)&r3.y);
        acc.x += v0 * a0.x; acc.y += v0 * a0.y; acc.z += v0 * b0.x; acc.w += v0 * b0.y;
        acc.x += v1 * a1.x; acc.y += v1 * a1.y; acc.z += v1 * b1.x; acc.w += v1 * b1.y;
        acc.x += v2 * a2.x; acc.y += v2 * a2.y; acc.z += v2 * b2.x; acc.w += v2 * b2.y;
        acc.x += v3 * a3.x; acc.y += v3 * a3.y; acc.z += v3 * b3.x; acc.w += v3 * b3.y;
    }
    for (; e < e1; e++) {
        int c = g_pcol[e];
        float v = g_pval[e];
        uint2 rr = *(const uint2*)(H + (size_t)c * F + lane * 4);
        float2 a = __half22float2(*(const __half2*)&rr.x), b = __half22float2(*(const __half2*)&rr.y);
        acc.x += v * a.x; acc.y += v * a.y; acc.z += v * b.x; acc.w += v * b.y;
    }
    uint2 o;
    *(__half2*)&o.x = __floats2half2_rn(acc.x, acc.y);
    *(__half2*)&o.y = __floats2half2_rn(acc.z, acc.w);
    *(uint2*)(out + (size_t)r * F + lane * 4) = o;
}

// ---------------- fused: row-restricted SPMM2 (fp16 gather) + linear + log_softmax ----------------
__global__ void spmm2_final(const __half* __restrict__ H2, const float* __restrict__ b2,
                            const float* __restrict__ s, const int* __restrict__ index,
                            const float* __restrict__ Wl, const float* __restrict__ bl,
                            float* __restrict__ out)
{
    __shared__ float Wls[(F + NSDIM) * NC];
    __shared__ float bls[NC];
    __shared__ float sin[8][F + NSDIM];

    for (int i = threadIdx.x; i < (F + NSDIM) * NC; i += blockDim.x) Wls[i] = Wl[i];
    if (threadIdx.x < NC) bls[threadIdx.x] = bl[threadIdx.x];
    __syncthreads();

    int warp = threadIdx.x >> 5;
    int lane = threadIdx.x & 31;
    int b = blockIdx.x * 8 + warp;
    if (b >= BQ) return;

    int r = __ldg(index + b);
    int e0 = g_ptr[r];
    int e1 = g_ptr[r + 1];

    float4 acc = make_float4(0.f, 0.f, 0.f, 0.f);
    int e = e0;
    for (; e + 4 <= e1; e += 4) {
        int   c0 = g_pcol[e],     c1 = g_pcol[e + 1], c2 = g_pcol[e + 2], c3 = g_pcol[e + 3];
        float v0 = g_pval[e],     v1 = g_pval[e + 1], v2 = g_pval[e + 2], v3 = g_pval[e + 3];
        uint2 r0 = *(const uint2*)(H2 + (size_t)c0 * F + lane * 4);
        uint2 r1 = *(const uint2*)(H2 + (size_t)c1 * F + lane * 4);
        uint2 r2 = *(const uint2*)(H2 + (size_t)c2 * F + lane * 4);
        uint2 r3 = *(const uint2*)(H2 + (size_t)c3 * F + lane * 4);
        float2 a0 = __half22float2(*(const __half2*)&r0.x), q0 = __half22float2(*(const __half2*)&r0.y);
        float2 a1 = __half22float2(*(const __half2*)&r1.x), q1 = __half22float2(*(const __half2*)&r1.y);
        float2 a2 = __half22float2(*(const __half2*)&r2.x), q2 = __half22float2(*(const __half2*)&r2.y);
        float2 a3 = __half22float2(*(const __half2*)&r3.x), q3 = __half22float2(*(const __half2*)&r3.y);
        acc.x += v0 * a0.x; acc.y += v0 * a0.y; acc.z += v0 * q0.x; acc.w += v0 * q0.y;
        acc.x += v1 * a1.x; acc.y += v1 * a1.y; acc.z += v1 * q1.x; acc.w += v1 * q1.y;
        acc.x += v2 * a2.x; acc.y += v2 * a2.y; acc.z += v2 * q2.x; acc.w += v2 * q2.y;
        acc.x += v3 * a3.x; acc.y += v3 * a3.y; acc.z += v3 * q3.x; acc.w += v3 * q3.y;
    }
    for (; e < e1; e++) {
        int c = g_pcol[e];
        float v = g_pval[e];
        uint2 rr = *(const uint2*)(H2 + (size_t)c * F + lane * 4);
        float2 a = __half22float2(*(const __half2*)&rr.x), q = __half22float2(*(const __half2*)&rr.y);
        acc.x += v * a.x; acc.y += v * a.y; acc.z += v * q.x; acc.w += v * q.y;
    }

    float4 bb = *(const float4*)(b2 + lane * 4);
    sin[warp][lane * 4 + 0] = acc.x + bb.x;
    sin[warp][lane * 4 + 1] = acc.y + bb.y;
    sin[warp][lane * 4 + 2] = acc.z + bb.z;
    sin[warp][lane * 4 + 3] = acc.w + bb.w;
    #pragma unroll
    for (int k = lane; k < NSDIM; k += 32)
        sin[warp][F + k] = s[(size_t)b * NSDIM + k];
    __syncwarp();

    float z = 0.f;
    if (lane < NC) {
        z = bls[lane];
        #pragma unroll 4
        for (int k = 0; k < F + NSDIM; k++)
            z += sin[warp][k] * Wls[k * NC + lane];
    }
    float m = z;
    #pragma unroll
    for (int o = 8; o > 0; o >>= 1)
        m = fmaxf(m, __shfl_xor_sync(0xffffffffu, m, o, 16));
    float ex = (lane < NC) ? expf(z - m) : 0.f;
    float sum = ex;
    #pragma unroll
    for (int o = 8; o > 0; o >>= 1)
        sum += __shfl_xor_sync(0xffffffffu, sum, o, 16);
    if (lane < NC)
        out[(size_t)b * NC + lane] = z - m - logf(sum);
}

// ---------------- launch ----------------
extern "C" void kernel_launch(void* const* d_in, const int* in_sizes, int n_in,
                              void* d_out, int out_size)
{
    const float* s    = (const float*)d_in[0];
    const float* x    = (const float*)d_in[1];
    const int*   row  = (const int*)  d_in[2];
    const int*   col  = (const int*)  d_in[3];
    const float* val  = (const float*)d_in[4];
    const int*   index= (const int*)  d_in[5];
    const float* W1   = (const float*)d_in[6];
    const float* b1   = (const float*)d_in[7];
    const float* W2   = (const float*)d_in[8];
    const float* b2   = (const float*)d_in[9];
    const float* Wl   = (const float*)d_in[10];
    const float* bl   = (const float*)d_in[11];
    float* out = (float*)d_out;

    __half *A, *B;
    int *cntp;
    cudaGetSymbolAddress((void**)&A, g_bufA);
    cudaGetSymbolAddress((void**)&B, g_bufB);
    cudaGetSymbolAddress((void**)&cntp, g_cnt);

    cudaFuncSetAttribute(gemm128_tc<false>, cudaFuncAttributeMaxDynamicSharedMemorySize, GEMM_SMEM);
    cudaFuncSetAttribute(gemm128_tc<true>,  cudaFuncAttributeMaxDynamicSharedMemorySize, GEMM_SMEM);

    const int gemm_grid  = (NN + 127) / 128;           // 782
    const int edge_grid  = (NEDGE + 255) / 256;        // 6250
    const int scan_nb    = (NN + 1023) / 1024;         // 98
    const int spmm_grid  = (NN + 7) / 8;               // 12500

    // ---- CSR build ----
    cudaMemsetAsync(cntp, 0, NN * sizeof(int));
    hist_kernel<<<edge_grid, 256>>>(row, NEDGE);
    scan1_kernel<<<scan_nb, 256>>>(NN);
    scan2_kernel<<<1, 256>>>(scan_nb);
    scan3_kernel<<<(NN + 255) / 256, 256>>>(NN, NEDGE);
    scatter_kernel<<<edge_grid, 256>>>(row, col, val, NEDGE);

    // ---- pipeline ----
    gemm128_tc<false><<<gemm_grid, 256, GEMM_SMEM>>>(x, W1, nullptr, A, NN);
    spmm_csr<<<spmm_grid, 256>>>(A, B);
    gemm128_tc<true><<<gemm_grid, 256, GEMM_SMEM>>>(B, W2, b1, A, NN);
    spmm2_final<<<(BQ + 7) / 8, 256>>>(A, b2, s, index, Wl, bl, out);
}

// round 6
// speedup vs baseline: 6.0675x; 1.0199x over previous
#include <cuda_runtime.h>
#include <cuda_fp16.h>
#include <cstdint>
#include <math.h>

#define NN      100000
#define NEDGE   1600000
#define F       128
#define BQ      8192
#define NSDIM   64
#define NC      16
#define SCAN_NB ((NN + 1023) / 1024)   // 98

// ---------------- scratch (__device__ globals, allocation-free) ----------------
__device__ __half g_bufA[(size_t)NN * F];
__device__ __half g_bufB[(size_t)NN * F];

struct CsrScratch {              // zeroed with ONE memset per launch
    int cnt[NN];
    int bsum[128];
    unsigned int ctr;
    unsigned int pad[3];
};
__device__ CsrScratch g_cs;
__device__ int   g_ptr[NN + 1];
__device__ int   g_woff[NN];
__device__ int   g_pcol[NEDGE];
__device__ float g_pval[NEDGE];

#define AS_STRIDE 132
#define WS_STRIDE 136
#define GEMM_SMEM ((128 * AS_STRIDE + 128 * WS_STRIDE) * 4)

__device__ __forceinline__ unsigned int f2tf32(float f) {
    unsigned int r;
    asm("cvt.rna.tf32.f32 %0, %1;" : "=r"(r) : "f"(f));
    return r;
}

// ---------------- tf32 tensor-core GEMM: C[M,128](fp16) = transform(X) @ W ----------------
// FUSE=false: X fp32.  FUSE=true: X fp16, relu(x + bias).
// DOHIST: append edge histogram (grid-stride) after the C store (overlaps with tensor work).
template <bool FUSE, bool DOHIST>
__global__ void gemm128_tc(const void* __restrict__ Xv, const float* __restrict__ W,
                           const float* __restrict__ bias, __half* __restrict__ C, int M,
                           const int* __restrict__ erow)
{
    extern __shared__ unsigned int smu[];
    unsigned int* As = smu;                    // [128][132]  [m][k]
    unsigned int* Ws = smu + 128 * AS_STRIDE;  // [128][136]  [k][n]

    const int tid  = threadIdx.x;          // 256 threads, 8 warps
    const int wid  = tid >> 5;
    const int lane = tid & 31;
    const int gid  = lane >> 2;
    const int tig  = lane & 3;
    const int wm   = wid & 3;
    const int wn   = wid >> 2;
    const int m0   = blockIdx.x * 128;

    #pragma unroll
    for (int i = 0; i < 16; i++) {
        int e = i * 256 + tid;
        int k = e >> 5;
        int n4 = (e & 31) << 2;
        float4 w = *(const float4*)(W + k * F + n4);
        uint4 u = make_uint4(f2tf32(w.x), f2tf32(w.y), f2tf32(w.z), f2tf32(w.w));
        *(uint4*)(Ws + k * WS_STRIDE + n4) = u;
    }

    if (FUSE) {
        const __half* Xh = (const __half*)Xv;
        #pragma unroll
        for (int i = 0; i < 8; i++) {
            int e = i * 256 + tid;
            int r = e >> 4;
            int kc = (e & 15) << 3;
            int m = m0 + r;
            uint4 raw = make_uint4(0u, 0u, 0u, 0u);
            if (m < M) raw = *(const uint4*)(Xh + (size_t)m * F + kc);
            const __half2* hp = (const __half2*)&raw;
            #pragma unroll
            for (int j = 0; j < 4; j++) {
                float2 f = __half22float2(hp[j]);
                float2 bb = *(const float2*)(bias + kc + j * 2);
                f.x = fmaxf(f.x + bb.x, 0.f);
                f.y = fmaxf(f.y + bb.y, 0.f);
                As[r * AS_STRIDE + kc + j * 2]     = f2tf32(f.x);
                As[r * AS_STRIDE + kc + j * 2 + 1] = f2tf32(f.y);
            }
        }
    } else {
        const float* Xf = (const float*)Xv;
        #pragma unroll
        for (int i = 0; i < 16; i++) {
            int e = i * 256 + tid;
            int r = e >> 5;
            int kc = (e & 31) << 2;
            int m = m0 + r;
            float4 v = make_float4(0.f, 0.f, 0.f, 0.f);
            if (m < M) v = *(const float4*)(Xf + (size_t)m * F + kc);
            uint4 u = make_uint4(f2tf32(v.x), f2tf32(v.y), f2tf32(v.z), f2tf32(v.w));
            *(uint4*)(As + r * AS_STRIDE + kc) = u;
        }
    }
    __syncthreads();

    float acc[2][8][4];
    #pragma unroll
    for (int a = 0; a < 2; a++)
        #pragma unroll
        for (int b = 0; b < 8; b++)
            #pragma unroll
            for (int c = 0; c < 4; c++) acc[a][b][c] = 0.f;

    #pragma unroll 4
    for (int ks = 0; ks < 16; ks++) {
        const int k0 = ks * 8;
        unsigned int afr[2][4];
        #pragma unroll
        for (int mf = 0; mf < 2; mf++) {
            int rb = wm * 32 + mf * 16 + gid;
            afr[mf][0] = As[rb * AS_STRIDE + k0 + tig];
            afr[mf][1] = As[(rb + 8) * AS_STRIDE + k0 + tig];
            afr[mf][2] = As[rb * AS_STRIDE + k0 + 4 + tig];
            afr[mf][3] = As[(rb + 8) * AS_STRIDE + k0 + 4 + tig];
        }
        unsigned int bfr[8][2];
        #pragma unroll
        for (int nf = 0; nf < 8; nf++) {
            int nb = wn * 64 + nf * 8 + gid;
            bfr[nf][0] = Ws[(k0 + tig) * WS_STRIDE + nb];
            bfr[nf][1] = Ws[(k0 + 4 + tig) * WS_STRIDE + nb];
        }
        #pragma unroll
        for (int mf = 0; mf < 2; mf++)
            #pragma unroll
            for (int nf = 0; nf < 8; nf++) {
                asm volatile(
                    "mma.sync.aligned.m16n8k8.row.col.f32.tf32.tf32.f32 "
                    "{%0,%1,%2,%3}, {%4,%5,%6,%7}, {%8,%9}, {%0,%1,%2,%3};"
                    : "+f"(acc[mf][nf][0]), "+f"(acc[mf][nf][1]),
                      "+f"(acc[mf][nf][2]), "+f"(acc[mf][nf][3])
                    : "r"(afr[mf][0]), "r"(afr[mf][1]), "r"(afr[mf][2]), "r"(afr[mf][3]),
                      "r"(bfr[nf][0]), "r"(bfr[nf][1]));
            }
    }

    #pragma unroll
    for (int mf = 0; mf < 2; mf++) {
        int r0 = m0 + wm * 32 + mf * 16 + gid;
        #pragma unroll
        for (int nf = 0; nf < 8; nf++) {
            int ccol = wn * 64 + nf * 8 + tig * 2;
            if (r0 < M)
                *(__half2*)(C + (size_t)r0 * F + ccol) =
                    __floats2half2_rn(acc[mf][nf][0], acc[mf][nf][1]);
            if (r0 + 8 < M)
                *(__half2*)(C + (size_t)(r0 + 8) * F + ccol) =
                    __floats2half2_rn(acc[mf][nf][2], acc[mf][nf][3]);
        }
    }

    if (DOHIST) {
        // Edge histogram, overlapped with other blocks' tensor work
        int stride = gridDim.x * blockDim.x;
        for (int e = blockIdx.x * blockDim.x + tid; e < NEDGE; e += stride)
            atomicAdd(&g_cs.cnt[erow[e]], 1);
    }
}

// ---------------- fused exclusive scan (single kernel, software grid barrier) ----------------
__global__ void scan_fused(int n, int ne)
{
    __shared__ int sm[256];
    __shared__ int wsum[8];
    __shared__ int s_prefix;
    const int tid = threadIdx.x;
    const int bid = blockIdx.x;
    const int nb  = gridDim.x;

    int base = bid * 1024 + tid * 4;
    int v[4];
    #pragma unroll
    for (int i = 0; i < 4; i++)
        v[i] = (base + i < n) ? g_cs.cnt[base + i] : 0;
    int tsum = v[0] + v[1] + v[2] + v[3];
    sm[tid] = tsum;
    __syncthreads();
    #pragma unroll
    for (int o = 1; o < 256; o <<= 1) {
        int t = (tid >= o) ? sm[tid - o] : 0;
        __syncthreads();
        sm[tid] += t;
        __syncthreads();
    }

    // publish block total, grid barrier via counter
    if (tid == 0) {
        ((volatile int*)g_cs.bsum)[bid] = sm[255];
        __threadfence();
        atomicAdd(&g_cs.ctr, 1u);
        while (((volatile unsigned int*)&g_cs.ctr)[0] < (unsigned)nb) {}
        __threadfence();
    }
    __syncthreads();

    // prefix = sum of bsum[0..bid-1], parallel reduce over 256 threads
    int p = (tid < bid) ? ((volatile int*)g_cs.bsum)[tid] : 0;
    #pragma unroll
    for (int o = 16; o; o >>= 1) p += __shfl_xor_sync(0xffffffffu, p, o);
    if ((tid & 31) == 0) wsum[tid >> 5] = p;
    __syncthreads();
    if (tid < 8) {
        int q = wsum[tid];
        #pragma unroll
        for (int o = 4; o; o >>= 1) q += __shfl_xor_sync(0xffu, q, o);
        if (tid == 0) s_prefix = q;
    }
    __syncthreads();

    int run = s_prefix + sm[tid] - tsum;
    #pragma unroll
    for (int i = 0; i < 4; i++) {
        if (base + i < n) { g_ptr[base + i] = run; g_woff[base + i] = run; }
        run += v[i];
    }
    if (bid == nb - 1 && tid == 0) g_ptr[n] = ne;
}

__global__ void scatter_kernel(const int* __restrict__ row, const int* __restrict__ col,
                               const float* __restrict__ val, int ne)
{
    int e = blockIdx.x * blockDim.x + threadIdx.x;
    if (e < ne) {
        int r = row[e];
        int p = atomicAdd(&g_woff[r], 1);
        g_pcol[p] = col[e];
        g_pval[p] = val[e];
    }
}

// ---------------- SPMM1: 16 lanes/row, 2 rows/warp, uint4 fp16 gathers ----------------
__global__ void spmm_csr(const __half* __restrict__ H, __half* __restrict__ out)
{
    const int tid  = threadIdx.x;     // 256 thr = 8 warps = 16 rows/block
    const int warp = tid >> 5;
    const int lane = tid & 31;
    const int half = lane >> 4;
    const int hl   = lane & 15;
    int r = blockIdx.x * 16 + warp * 2 + half;
    if (r >= NN) return;

    int e0 = g_ptr[r];
    int e1 = g_ptr[r + 1];

    float acc[8] = {0.f, 0.f, 0.f, 0.f, 0.f, 0.f, 0.f, 0.f};
    const size_t off = (size_t)hl * 8;

    int e = e0;
    for (; e + 4 <= e1; e += 4) {
        int   c0 = g_pcol[e],     c1 = g_pcol[e + 1], c2 = g_pcol[e + 2], c3 = g_pcol[e + 3];
        float v0 = g_pval[e],     v1 = g_pval[e + 1], v2 = g_pval[e + 2], v3 = g_pval[e + 3];
        uint4 r0 = *(const uint4*)(H + (size_t)c0 * F + off);
        uint4 r1 = *(const uint4*)(H + (size_t)c1 * F + off);
        uint4 r2 = *(const uint4*)(H + (size_t)c2 * F + off);
        uint4 r3 = *(const uint4*)(H + (size_t)c3 * F + off);
        const __half2* h0 = (const __half2*)&r0;
        const __half2* h1 = (const __half2*)&r1;
        const __half2* h2 = (const __half2*)&r2;
        const __half2* h3 = (const __half2*)&r3;
        #pragma unroll
        for (int j = 0; j < 4; j++) {
            float2 f0 = __half22float2(h0[j]);
            float2 f1 = __half22float2(h1[j]);
            float2 f2 = __half22float2(h2[j]);
            float2 f3 = __half22float2(h3[j]);
            acc[j*2]   += v0 * f0.x + v1 * f1.x + v2 * f2.x + v3 * f3.x;
            acc[j*2+1] += v0 * f0.y + v1 * f1.y + v2 * f2.y + v3 * f3.y;
        }
    }
    for (; e < e1; e++) {
        int c = g_pcol[e];
        float v = g_pval[e];
        uint4 rr = *(const uint4*)(H + (size_t)c * F + off);
        const __half2* hh = (const __half2*)&rr;
        #pragma unroll
        for (int j = 0; j < 4; j++) {
            float2 f = __half22float2(hh[j]);
            acc[j*2]   += v * f.x;
            acc[j*2+1] += v * f.y;
        }
    }
    uint4 o;
    __half2* op = (__half2*)&o;
    #pragma unroll
    for (int j = 0; j < 4; j++)
        op[j] = __floats2half2_rn(acc[j*2], acc[j*2+1]);
    *(uint4*)(out + (size_t)r * F + off) = o;
}

// ---------------- fused: row-restricted SPMM2 + linear + log_softmax (half-warp/sample) ----------------
__global__ void spmm2_final(const __half* __restrict__ H2, const float* __restrict__ b2,
                            const float* __restrict__ s, const int* __restrict__ index,
                            const float* __restrict__ Wl, const float* __restrict__ bl,
                            float* __restrict__ out)
{
    __shared__ float Wls[(F + NSDIM) * NC];
    __shared__ float bls[NC];
    __shared__ float sin[16][F + NSDIM];

    for (int i = threadIdx.x; i < (F + NSDIM) * NC; i += blockDim.x) Wls[i] = Wl[i];
    if (threadIdx.x < NC) bls[threadIdx.x] = bl[threadIdx.x];
    __syncthreads();

    const int tid  = threadIdx.x;     // 256 thr = 8 warps = 16 samples/block
    const int warp = tid >> 5;
    const int lane = tid & 31;
    const int half = lane >> 4;
    const int hl   = lane & 15;
    const int sidx = warp * 2 + half;
    int b = blockIdx.x * 16 + sidx;
    if (b >= BQ) return;

    int r = __ldg(index + b);
    int e0 = g_ptr[r];
    int e1 = g_ptr[r + 1];

    float acc[8] = {0.f, 0.f, 0.f, 0.f, 0.f, 0.f, 0.f, 0.f};
    const size_t off = (size_t)hl * 8;

    int e = e0;
    for (; e + 4 <= e1; e += 4) {
        int   c0 = g_pcol[e],     c1 = g_pcol[e + 1], c2 = g_pcol[e + 2], c3 = g_pcol[e + 3];
        float v0 = g_pval[e],     v1 = g_pval[e + 1], v2 = g_pval[e + 2], v3 = g_pval[e + 3];
        uint4 r0 = *(const uint4*)(H2 + (size_t)c0 * F + off);
        uint4 r1 = *(const uint4*)(H2 + (size_t)c1 * F + off);
        uint4 r2 = *(const uint4*)(H2 + (size_t)c2 * F + off);
        uint4 r3 = *(const uint4*)(H2 + (size_t)c3 * F + off);
        const __half2* h0 = (const __half2*)&r0;
        const __half2* h1 = (const __half2*)&r1;
        const __half2* h2 = (const __half2*)&r2;
        const __half2* h3 = (const __half2*)&r3;
        #pragma unroll
        for (int j = 0; j < 4; j++) {
            float2 f0 = __half22float2(h0[j]);
            float2 f1 = __half22float2(h1[j]);
            float2 f2 = __half22float2(h2[j]);
            float2 f3 = __half22float2(h3[j]);
            acc[j*2]   += v0 * f0.x + v1 * f1.x + v2 * f2.x + v3 * f3.x;
            acc[j*2+1] += v0 * f0.y + v1 * f1.y + v2 * f2.y + v3 * f3.y;
        }
    }
    for (; e < e1; e++) {
        int c = g_pcol[e];
        float v = g_pval[e];
        uint4 rr = *(const uint4*)(H2 + (size_t)c * F + off);
        const __half2* hh = (const __half2*)&rr;
        #pragma unroll
        for (int j = 0; j < 4; j++) {
            float2 f = __half22float2(hh[j]);
            acc[j*2]   += v * f.x;
            acc[j*2+1] += v * f.y;
        }
    }

    // concat input vector in shared
    #pragma unroll
    for (int j = 0; j < 8; j++)
        sin[sidx][hl * 8 + j] = acc[j] + b2[hl * 8 + j];
    #pragma unroll
    for (int j = 0; j < 4; j++)
        sin[sidx][F + hl * 4 + j] = s[(size_t)b * NSDIM + hl * 4 + j];
    __syncwarp();

    // each of the 16 lanes in this half computes one class
    float z = bls[hl];
    #pragma unroll 4
    for (int k = 0; k < F + NSDIM; k++)
        z += sin[sidx][k] * Wls[k * NC + hl];

    // log_softmax within the 16-lane half (width-16 shuffles segment at halves)
    float m = z;
    #pragma unroll
    for (int o = 8; o > 0; o >>= 1)
        m = fmaxf(m, __shfl_xor_sync(0xffffffffu, m, o, 16));
    float ex = expf(z - m);
    float sum = ex;
    #pragma unroll
    for (int o = 8; o > 0; o >>= 1)
        sum += __shfl_xor_sync(0xffffffffu, sum, o, 16);
    out[(size_t)b * NC + hl] = z - m - logf(sum);
}

// ---------------- launch ----------------
extern "C" void kernel_launch(void* const* d_in, const int* in_sizes, int n_in,
                              void* d_out, int out_size)
{
    const float* s    = (const float*)d_in[0];
    const float* x    = (const float*)d_in[1];
    const int*   row  = (const int*)  d_in[2];
    const int*   col  = (const int*)  d_in[3];
    const float* val  = (const float*)d_in[4];
    const int*   index= (const int*)  d_in[5];
    const float* W1   = (const float*)d_in[6];
    const float* b1   = (const float*)d_in[7];
    const float* W2   = (const float*)d_in[8];
    const float* b2   = (const float*)d_in[9];
    const float* Wl   = (const float*)d_in[10];
    const float* bl   = (const float*)d_in[11];
    float* out = (float*)d_out;

    __half *A, *B;
    void *csp;
    cudaGetSymbolAddress((void**)&A, g_bufA);
    cudaGetSymbolAddress((void**)&B, g_bufB);
    cudaGetSymbolAddress(&csp, g_cs);

    cudaFuncSetAttribute((const void*)gemm128_tc<false, true>,  cudaFuncAttributeMaxDynamicSharedMemorySize, GEMM_SMEM);
    cudaFuncSetAttribute((const void*)gemm128_tc<true, false>,  cudaFuncAttributeMaxDynamicSharedMemorySize, GEMM_SMEM);

    const int gemm_grid  = (NN + 127) / 128;           // 782
    const int edge_grid  = (NEDGE + 255) / 256;        // 6250
    const int spmm_grid  = (NN + 15) / 16;             // 6250

    // zero cnt + bsum + ctr in one memset
    cudaMemsetAsync(csp, 0, sizeof(CsrScratch));

    // GEMM1 (+ fused edge histogram)
    gemm128_tc<false, true><<<gemm_grid, 256, GEMM_SMEM>>>(x, W1, nullptr, A, NN, row);

    // scan (fused, one kernel) + scatter
    scan_fused<<<SCAN_NB, 256>>>(NN, NEDGE);
    scatter_kernel<<<edge_grid, 256>>>(row, col, val, NEDGE);

    // SPMM1, GEMM2, fused SPMM2+final
    spmm_csr<<<spmm_grid, 256>>>(A, B);
    gemm128_tc<true, false><<<gemm_grid, 256, GEMM_SMEM>>>(B, W2, b1, A, NN, nullptr);
    spmm2_final<<<(BQ + 15) / 16, 256>>>(A, b2, s, index, Wl, bl, out);
}